// round 13
// baseline (speedup 1.0000x reference)
#include <cuda_runtime.h>
#include <cuda_bf16.h>
#include <cstdint>

#define DD 128
#define MAXN 50000
#define MAXE 600000
#define GG 64

// ---------------- scratch (static device globals; no runtime allocation) ----
__device__ float g_agg[MAXN * DD];
__device__ float g_h0[MAXN * DD];
__device__ float g_h1[MAXN * DD];
__device__ int   g_deg[MAXN];
__device__ int   g_off[MAXN + 1];
__device__ int   g_cur[MAXN];
__device__ int   g_csr[MAXE];
__device__ int   g_src[MAXE];
__device__ int   g_dst[MAXE];
__device__ int   g_gstart[GG + 1];
__device__ float g_pool[GG * DD];
__device__ int   g_e32;
__device__ int   g_b32;
__device__ int   g_bsum[64];
// fragment-linear bf16 weights: [layer][seg][8192 u32]
// seg: 0=rel_hi, 1=rel_lo, 2=root_hi, 3=root_lo
// u32 index r: vec = r>>2, c = r&3; lane = vec&31, i8 = (vec>>5)&7, ks = vec>>8
// ntile = 2*i8 + (c>>1), j = c&1; n = ntile*8 + lane/4,
// kb = ks*16 + (lane%4)*2 + j*8 ; value = bf16x2{W[n][kb], W[n][kb+1]}
__device__ __align__(16) uint32_t g_wlin[3][4][8192];

// bf16x2 pack: low16 = bf16(a), high16 = bf16(b)
__device__ __forceinline__ uint32_t bfhi(float a, float b) {
    uint32_t r;
    asm("cvt.rn.bf16x2.f32 %0, %1, %2;" : "=r"(r) : "f"(b), "f"(a));
    return r;
}
// residual pair given the hi pack
__device__ __forceinline__ uint32_t bflo(float a, float b, uint32_t hi) {
    float fa = __uint_as_float(hi << 16);
    float fb = __uint_as_float(hi & 0xFFFF0000u);
    return bfhi(a - fa, b - fb);
}

// ---------------- preprocessing ---------------------------------------------

// init degrees + dtype detection (block 0 samples both raw arrays)
__global__ void k_init(const int* __restrict__ eraw, const int* __restrict__ braw,
                       int E, int Nb, int N) {
    int i = blockIdx.x * blockDim.x + threadIdx.x;
    if (i < N) g_deg[i] = 0;
    if (i == 0) { g_e32 = 0; g_b32 = 0; }
    if (blockIdx.x == 0) {
        long ie = ((long)threadIdx.x * E)  >> 8;
        long ib = ((long)threadIdx.x * Nb) >> 8;
        if (threadIdx.x < 256) {
            if (ie < E  && eraw[2 * ie + 1] != 0) g_e32 = 1;
            if (ib < Nb && braw[2 * ib + 1] != 0) g_b32 = 1;
        }
    }
}

__global__ void k_edges(const int* __restrict__ raw, int E) {
    int e = blockIdx.x * blockDim.x + threadIdx.x;
    if (e >= E) return;
    int s, d;
    if (g_e32) { s = raw[e];     d = raw[E + e]; }
    else       { s = raw[2 * e]; d = raw[2 * (E + e)]; }
    g_src[e] = s;
    g_dst[e] = d;
    atomicAdd(&g_deg[d], 1);
}

__global__ void k_batch(const int* __restrict__ raw, int N, int G) {
    int i = blockIdx.x * blockDim.x + threadIdx.x;
    if (i >= N) return;
    int b  = g_b32 ? raw[i] : raw[2 * i];
    int pb = (i == 0) ? -1 : (g_b32 ? raw[i - 1] : raw[2 * (i - 1)]);
    for (int g = pb + 1; g <= b; ++g) g_gstart[g] = i;
    if (i == N - 1)
        for (int g = b + 1; g <= G; ++g) g_gstart[g] = N;
}

__global__ void k_scan1(int N) {
    __shared__ int sw[32];
    int tid = threadIdx.x, lane = tid & 31, w = tid >> 5;
    int i = blockIdx.x * 1024 + tid;
    int v = (i < N) ? g_deg[i] : 0;
#pragma unroll
    for (int d = 16; d > 0; d >>= 1) v += __shfl_down_sync(0xffffffffu, v, d);
    if (lane == 0) sw[w] = v;
    __syncthreads();
    if (w == 0) {
        v = sw[lane];
#pragma unroll
        for (int d = 16; d > 0; d >>= 1) v += __shfl_down_sync(0xffffffffu, v, d);
        if (lane == 0) g_bsum[blockIdx.x] = v;
    }
}

__global__ void k_scan2(int nsb) {
    if (threadIdx.x == 0) {
        int a = 0;
        for (int b = 0; b < nsb; ++b) { int t = g_bsum[b]; g_bsum[b] = a; a += t; }
    }
}

__global__ void k_scan3(int N) {
    __shared__ int sw[32];
    int tid = threadIdx.x, lane = tid & 31, w = tid >> 5;
    int i = blockIdx.x * 1024 + tid;
    int v = (i < N) ? g_deg[i] : 0;
    int x = v;
#pragma unroll
    for (int d = 1; d < 32; d <<= 1) {
        int t = __shfl_up_sync(0xffffffffu, x, d);
        if (lane >= d) x += t;
    }
    if (lane == 31) sw[w] = x;
    __syncthreads();
    if (w == 0) {
        int y = sw[lane];
#pragma unroll
        for (int d = 1; d < 32; d <<= 1) {
            int t = __shfl_up_sync(0xffffffffu, y, d);
            if (lane >= d) y += t;
        }
        sw[lane] = y;
    }
    __syncthreads();
    x += ((w > 0) ? sw[w - 1] : 0) + g_bsum[blockIdx.x];
    if (i < N) { g_off[i + 1] = x; g_cur[i] = x - v; }
    if (i == 0) g_off[0] = 0;
}

__global__ void k_fill(int E) {
    int e = blockIdx.x * blockDim.x + threadIdx.x;
    if (e >= E) return;
    int p = atomicAdd(&g_cur[g_dst[e]], 1);
    g_csr[p] = g_src[e];
}

// ---------------- weight prep: all 6 matrices, one launch ---------------------
__global__ void k_wprep(const float* __restrict__ W0, const float* __restrict__ W1m,
                        const float* __restrict__ W2m, const float* __restrict__ W3,
                        const float* __restrict__ W4, const float* __restrict__ W5) {
    int i = blockIdx.x * blockDim.x + threadIdx.x;
    if (i >= 6 * 8192) return;
    int w = i >> 13;
    const float* W = (w == 0) ? W0 : (w == 1) ? W1m : (w == 2) ? W2m
                   : (w == 3) ? W3 : (w == 4) ? W4 : W5;
    int layer = w >> 1, mat = w & 1;
    int r    = i & 8191;
    int c    = r & 3;
    int vec  = r >> 2;
    int lane = vec & 31;
    int i8   = (vec >> 5) & 7;
    int ks   = vec >> 8;
    int nt = 2 * i8 + (c >> 1);
    int j  = c & 1;
    int n  = nt * 8 + (lane >> 2);
    int kb = ks * 16 + (lane & 3) * 2 + j * 8;
    float w0 = W[n * 128 + kb];
    float w1 = W[n * 128 + kb + 1];
    uint32_t hi = bfhi(w0, w1);
    uint32_t lo = bflo(w0, w1, hi);
    g_wlin[layer][mat * 2 + 0][r] = hi;
    g_wlin[layer][mat * 2 + 1][r] = lo;
}

// ---------------- gather -----------------------------------------------------

__global__ void k_gather(const float* __restrict__ xin, int sel, int N) {
    int warp = (blockIdx.x * blockDim.x + threadIdx.x) >> 5;
    int lane = threadIdx.x & 31;
    if (warp >= N) return;
    const float* H = (sel == 0) ? xin : (sel == 1 ? g_h0 : g_h1);
    const float4* H4 = reinterpret_cast<const float4*>(H);
    int s = g_off[warp], e = g_off[warp + 1];
    float4 acc = make_float4(0.f, 0.f, 0.f, 0.f);
    int i = s;
    for (; i + 2 <= e; i += 2) {
        int s0 = g_csr[i], s1 = g_csr[i + 1];
        float4 v0 = H4[s0 * 32 + lane];
        float4 v1 = H4[s1 * 32 + lane];
        acc.x += v0.x + v1.x; acc.y += v0.y + v1.y;
        acc.z += v0.z + v1.z; acc.w += v0.w + v1.w;
    }
    if (i < e) {
        float4 v = H4[g_csr[i] * 32 + lane];
        acc.x += v.x; acc.y += v.y; acc.z += v.z; acc.w += v.w;
    }
    reinterpret_cast<float4*>(g_agg)[warp * 32 + lane] = acc;
}

// ---------------- fused HMMA dual-GEMM layer ---------------------------------
// out = agg @ Wrel^T + h @ Wroot^T + bias [, relu]
// bf16-pair split (AhWh + AhWl + AlWh), f32 accumulate, mma.sync m16n8k16.
// CTA: 256 threads, 8 warps x 32 rows = 256-row tile, 128 cols.
// All 4 W segments staged once in dynamic smem (128 KB), conflict-free LDS.128.

__device__ __forceinline__ void mma16816(float* d, const uint32_t* a,
                                         uint32_t b0, uint32_t b1) {
    asm volatile(
        "mma.sync.aligned.m16n8k16.row.col.f32.bf16.bf16.f32 "
        "{%0,%1,%2,%3}, {%4,%5,%6,%7}, {%8,%9}, {%0,%1,%2,%3};"
        : "+f"(d[0]), "+f"(d[1]), "+f"(d[2]), "+f"(d[3])
        : "r"(a[0]), "r"(a[1]), "r"(a[2]), "r"(a[3]), "r"(b0), "r"(b1));
}

#define HM_SMEM (4 * 8192 * 4)   // 131072 B

__global__ void __launch_bounds__(256, 1) k_hmma(
    const float* __restrict__ xin, int selIn, int selOut,
    int layer, const float* __restrict__ bias, int N, int do_relu)
{
    extern __shared__ uint4 sw4[];   // [4 segs][2048 uint4]
    const int tid  = threadIdx.x;
    const int wid  = tid >> 5;
    const int lane = tid & 31;

    // stage all 4 W segments (128 KB) into smem
    {
        const uint4* src = reinterpret_cast<const uint4*>(g_wlin[layer]);
#pragma unroll
        for (int t = 0; t < 32; ++t) sw4[tid + t * 256] = src[tid + t * 256];
    }
    __syncthreads();

    const float* Hin = (selIn == 0) ? xin : (selIn == 1 ? g_h0 : g_h1);
    float* Hout = (selOut == 1) ? g_h0 : g_h1;

    const int row0  = blockIdx.x * 256 + wid * 32;
    const int rbase = row0 + (lane >> 2);
    const int kc    = (lane & 3) * 2;

    float acc[32][4];
#pragma unroll
    for (int t = 0; t < 32; ++t)
#pragma unroll
        for (int j = 0; j < 4; ++j) acc[t][j] = 0.f;

    uint32_t Ah[8], Al[8];

#pragma unroll 1
    for (int s = 0; s < 2; ++s) {
        const float* Asrc = s ? Hin : g_agg;
        const uint4* segHi = sw4 + (s * 2 + 0) * 2048;
        const uint4* segLo = sw4 + (s * 2 + 1) * 2048;

#pragma unroll 1
        for (int ks = 0; ks < 8; ++ks) {
            const int k0 = ks * 16 + kc;
            // build A hi/lo frags for both 16-row m-tiles
#pragma unroll
            for (int mt = 0; mt < 2; ++mt) {
                int ra = rbase + mt * 16, rb = ra + 8;
                bool va = ra < N, vb = rb < N;
                const float* pa = Asrc + (size_t)ra * 128;
                const float* pb = Asrc + (size_t)rb * 128;
                float2 z = make_float2(0.f, 0.f);
                float2 x0 = va ? *(const float2*)(pa + k0)     : z;
                float2 x1 = vb ? *(const float2*)(pb + k0)     : z;
                float2 x2 = va ? *(const float2*)(pa + k0 + 8) : z;
                float2 x3 = vb ? *(const float2*)(pb + k0 + 8) : z;
                uint32_t h0 = bfhi(x0.x, x0.y), h1 = bfhi(x1.x, x1.y);
                uint32_t h2 = bfhi(x2.x, x2.y), h3 = bfhi(x3.x, x3.y);
                Ah[mt * 4 + 0] = h0; Al[mt * 4 + 0] = bflo(x0.x, x0.y, h0);
                Ah[mt * 4 + 1] = h1; Al[mt * 4 + 1] = bflo(x1.x, x1.y, h1);
                Ah[mt * 4 + 2] = h2; Al[mt * 4 + 2] = bflo(x2.x, x2.y, h2);
                Ah[mt * 4 + 3] = h3; Al[mt * 4 + 3] = bflo(x3.x, x3.y, h3);
            }
            const uint4* rowHi = segHi + ks * 8 * 32 + lane;
            const uint4* rowLo = segLo + ks * 8 * 32 + lane;
            // pass 1: Ah x W_hi
#pragma unroll
            for (int i = 0; i < 8; ++i) {
                uint4 q = rowHi[i * 32];
                mma16816(acc[2 * i],          Ah,     q.x, q.y);
                mma16816(acc[2 * i + 1],      Ah,     q.z, q.w);
                mma16816(acc[16 + 2 * i],     Ah + 4, q.x, q.y);
                mma16816(acc[16 + 2 * i + 1], Ah + 4, q.z, q.w);
            }
            // pass 2: Ah x W_lo
#pragma unroll
            for (int i = 0; i < 8; ++i) {
                uint4 q = rowLo[i * 32];
                mma16816(acc[2 * i],          Ah,     q.x, q.y);
                mma16816(acc[2 * i + 1],      Ah,     q.z, q.w);
                mma16816(acc[16 + 2 * i],     Ah + 4, q.x, q.y);
                mma16816(acc[16 + 2 * i + 1], Ah + 4, q.z, q.w);
            }
            // pass 3: Al x W_hi
#pragma unroll
            for (int i = 0; i < 8; ++i) {
                uint4 q = rowHi[i * 32];
                mma16816(acc[2 * i],          Al,     q.x, q.y);
                mma16816(acc[2 * i + 1],      Al,     q.z, q.w);
                mma16816(acc[16 + 2 * i],     Al + 4, q.x, q.y);
                mma16816(acc[16 + 2 * i + 1], Al + 4, q.z, q.w);
            }
        }
    }

    // ---- epilogue: bias, relu, store ----
#pragma unroll
    for (int mt = 0; mt < 2; ++mt) {
        int ra = rbase + mt * 16, rb = ra + 8;
        bool va = ra < N, vb = rb < N;
#pragma unroll
        for (int nt = 0; nt < 16; ++nt) {
            int c = nt * 8 + kc;
            float2 bv = *(const float2*)(bias + c);
            float* d = acc[mt * 16 + nt];
            float o0 = d[0] + bv.x, o1 = d[1] + bv.y;
            float o2 = d[2] + bv.x, o3 = d[3] + bv.y;
            if (do_relu) {
                o0 = fmaxf(o0, 0.f); o1 = fmaxf(o1, 0.f);
                o2 = fmaxf(o2, 0.f); o3 = fmaxf(o3, 0.f);
            }
            if (va) *(float2*)(Hout + (size_t)ra * 128 + c) = make_float2(o0, o1);
            if (vb) *(float2*)(Hout + (size_t)rb * 128 + c) = make_float2(o2, o3);
        }
    }
}

// ---------------- pooling + MLP ---------------------------------------------

__global__ void k_pool() {
    int g     = blockIdx.x;
    int chunk = blockIdx.y;
    int lane  = threadIdx.x & 31;
    int grp   = threadIdx.x >> 5;
    int col   = chunk * 32 + lane;
    int s = g_gstart[g], e = g_gstart[g + 1];
    float m = -3.402823466e38f;
    for (int r = s + grp; r < e; r += 8)
        m = fmaxf(m, g_h0[(long)r * 128 + col]);
    __shared__ float smx[8][32];
    smx[grp][lane] = m;
    __syncthreads();
    if (grp == 0) {
#pragma unroll
        for (int i = 1; i < 8; ++i) m = fmaxf(m, smx[i][lane]);
        g_pool[g * 128 + col] = m;
    }
}

__global__ void k_mlp(const float* __restrict__ W1, const float* __restrict__ b1,
                      const float* __restrict__ W2, const float* __restrict__ b2,
                      float* __restrict__ out, int G) {
    int g = threadIdx.x;
    if (g >= G) return;
    float o = b2[0];
#pragma unroll
    for (int j = 0; j < 5; ++j) {
        float s = b1[j];
        for (int k = 0; k < DD; k += 4) {
            float4 p  = reinterpret_cast<const float4*>(g_pool + g * DD)[k >> 2];
            float4 ww = reinterpret_cast<const float4*>(W1 + j * DD)[k >> 2];
            s += p.x * ww.x + p.y * ww.y + p.z * ww.z + p.w * ww.w;
        }
        o += fmaxf(s, 0.f) * W2[j];
    }
    out[g] = o;
}

// ---------------- launch -----------------------------------------------------

extern "C" void kernel_launch(void* const* d_in, const int* in_sizes, int n_in,
                              void* d_out, int out_size) {
    const float* x    = (const float*)d_in[0];
    const int*   eraw = (const int*)d_in[1];
    const int*   braw = (const int*)d_in[2];
    const float* Wr1  = (const float*)d_in[3];
    const float* br1  = (const float*)d_in[4];
    const float* Wo1  = (const float*)d_in[5];
    const float* Wr2  = (const float*)d_in[6];
    const float* br2  = (const float*)d_in[7];
    const float* Wo2  = (const float*)d_in[8];
    const float* Wr3  = (const float*)d_in[9];
    const float* br3  = (const float*)d_in[10];
    const float* Wo3  = (const float*)d_in[11];
    const float* W1   = (const float*)d_in[12];
    const float* b1   = (const float*)d_in[13];
    const float* W2   = (const float*)d_in[14];
    const float* b2   = (const float*)d_in[15];
    float* out = (float*)d_out;

    const int N = in_sizes[0] / DD;
    const int E = in_sizes[1] / 2;
    const int G = out_size;

    const int nb  = (N + 255) / 256;
    const int eb  = (E + 255) / 256;
    const int nsb = (N + 1023) / 1024;
    const int gw  = (N + 7) / 8;
    const int nt256 = (N + 255) / 256;

    static cudaStream_t s2 = nullptr;
    static cudaEvent_t evFork, evW;
    if (!s2) {
        cudaStreamCreateWithFlags(&s2, cudaStreamNonBlocking);
        cudaEventCreateWithFlags(&evFork, cudaEventDisableTiming);
        cudaEventCreateWithFlags(&evW,    cudaEventDisableTiming);
        cudaFuncSetAttribute(k_hmma, cudaFuncAttributeMaxDynamicSharedMemorySize,
                             HM_SMEM);
    }

    // ---- weight prep on s2, overlapped with CSR preprocessing ----
    cudaEventRecord(evFork, 0);
    cudaStreamWaitEvent(s2, evFork, 0);
    k_wprep<<<192, 256, 0, s2>>>(Wr1, Wo1, Wr2, Wo2, Wr3, Wo3);
    cudaEventRecord(evW, s2);

    // ---- CSR + batch preprocessing ----
    k_init<<<nb, 256>>>(eraw, braw, E, N / 2, N);
    k_edges<<<eb, 256>>>(eraw, E);
    k_batch<<<nb, 256>>>(braw, N, G);
    k_scan1<<<nsb, 1024>>>(N);
    k_scan2<<<1, 32>>>(nsb);
    k_scan3<<<nsb, 1024>>>(N);
    k_fill<<<eb, 256>>>(E);

    // ---- layer 1 ----
    k_gather<<<gw, 256>>>(x, 0, N);
    cudaStreamWaitEvent(0, evW, 0);
    k_hmma<<<nt256, 256, HM_SMEM>>>(x, 0, 1, 0, br1, N, 1); // h0 = relu(agg@Wr1^T + x@Wo1^T + b1)
    // ---- layer 2 ----
    k_gather<<<gw, 256>>>(x, 1, N);
    k_hmma<<<nt256, 256, HM_SMEM>>>(x, 1, 2, 1, br2, N, 1); // h1 = relu(agg@Wr2^T + h0@Wo2^T + b2)
    // ---- layer 3 ----
    k_gather<<<gw, 256>>>(x, 2, N);
    k_hmma<<<nt256, 256, HM_SMEM>>>(x, 2, 1, 2, br3, N, 0); // h0 = agg@Wr3^T + h1@Wo3^T + b3

    // ---- pool + mlp ----
    dim3 pg(G, DD / 32);
    k_pool<<<pg, 256>>>();
    k_mlp<<<1, 64>>>(W1, b1, W2, b2, out, G);
}

// round 14
// speedup vs baseline: 1.0063x; 1.0063x over previous
#include <cuda_runtime.h>
#include <cuda_bf16.h>
#include <cstdint>

#define DD 128
#define MAXN 50000
#define MAXE 600000
#define GG 64

// ---------------- scratch (static device globals; no runtime allocation) ----
__device__ float g_agg[MAXN * DD];
__device__ float g_h0[MAXN * DD];
__device__ float g_h1[MAXN * DD];
__device__ int   g_deg[MAXN];
__device__ int   g_off[MAXN + 1];
__device__ int   g_cur[MAXN];
__device__ int   g_csr[MAXE];
__device__ int   g_src[MAXE];
__device__ int   g_dst[MAXE];
__device__ int   g_gstart[GG + 1];
__device__ float g_pool[GG * DD];
__device__ int   g_e32;
__device__ int   g_b32;
__device__ int   g_bsum[64];
// fragment-linear bf16 weights: [layer][seg][8192 u32]
// seg: 0=rel_hi, 1=rel_lo, 2=root_hi, 3=root_lo
// u32 index r: vec = r>>2, c = r&3; lane = vec&31, i8 = (vec>>5)&7, ks = vec>>8
// ntile = 2*i8 + (c>>1), j = c&1; n = ntile*8 + lane/4,
// kb = ks*16 + (lane%4)*2 + j*8 ; value = bf16x2{W[n][kb], W[n][kb+1]}
__device__ __align__(16) uint32_t g_wlin[3][4][8192];

// bf16x2 pack: low16 = bf16(a), high16 = bf16(b)
__device__ __forceinline__ uint32_t bfhi(float a, float b) {
    uint32_t r;
    asm("cvt.rn.bf16x2.f32 %0, %1, %2;" : "=r"(r) : "f"(b), "f"(a));
    return r;
}
// residual pair given the hi pack
__device__ __forceinline__ uint32_t bflo(float a, float b, uint32_t hi) {
    float fa = __uint_as_float(hi << 16);
    float fb = __uint_as_float(hi & 0xFFFF0000u);
    return bfhi(a - fa, b - fb);
}

// ---------------- preprocessing ---------------------------------------------

// init degrees + dtype detection (block 0 samples both raw arrays)
__global__ void k_init(const int* __restrict__ eraw, const int* __restrict__ braw,
                       int E, int Nb, int N) {
    int i = blockIdx.x * blockDim.x + threadIdx.x;
    if (i < N) g_deg[i] = 0;
    if (i == 0) { g_e32 = 0; g_b32 = 0; }
    if (blockIdx.x == 0) {
        long ie = ((long)threadIdx.x * E)  >> 8;
        long ib = ((long)threadIdx.x * Nb) >> 8;
        if (threadIdx.x < 256) {
            if (ie < E  && eraw[2 * ie + 1] != 0) g_e32 = 1;
            if (ib < Nb && braw[2 * ib + 1] != 0) g_b32 = 1;
        }
    }
}

__global__ void k_edges(const int* __restrict__ raw, int E) {
    int e = blockIdx.x * blockDim.x + threadIdx.x;
    if (e >= E) return;
    int s, d;
    if (g_e32) { s = raw[e];     d = raw[E + e]; }
    else       { s = raw[2 * e]; d = raw[2 * (E + e)]; }
    g_src[e] = s;
    g_dst[e] = d;
    atomicAdd(&g_deg[d], 1);
}

__global__ void k_batch(const int* __restrict__ raw, int N, int G) {
    int i = blockIdx.x * blockDim.x + threadIdx.x;
    if (i >= N) return;
    int b  = g_b32 ? raw[i] : raw[2 * i];
    int pb = (i == 0) ? -1 : (g_b32 ? raw[i - 1] : raw[2 * (i - 1)]);
    for (int g = pb + 1; g <= b; ++g) g_gstart[g] = i;
    if (i == N - 1)
        for (int g = b + 1; g <= G; ++g) g_gstart[g] = N;
}

__global__ void k_scan1(int N) {
    __shared__ int sw[32];
    int tid = threadIdx.x, lane = tid & 31, w = tid >> 5;
    int i = blockIdx.x * 1024 + tid;
    int v = (i < N) ? g_deg[i] : 0;
#pragma unroll
    for (int d = 16; d > 0; d >>= 1) v += __shfl_down_sync(0xffffffffu, v, d);
    if (lane == 0) sw[w] = v;
    __syncthreads();
    if (w == 0) {
        v = sw[lane];
#pragma unroll
        for (int d = 16; d > 0; d >>= 1) v += __shfl_down_sync(0xffffffffu, v, d);
        if (lane == 0) g_bsum[blockIdx.x] = v;
    }
}

__global__ void k_scan2(int nsb) {
    if (threadIdx.x == 0) {
        int a = 0;
        for (int b = 0; b < nsb; ++b) { int t = g_bsum[b]; g_bsum[b] = a; a += t; }
    }
}

__global__ void k_scan3(int N) {
    __shared__ int sw[32];
    int tid = threadIdx.x, lane = tid & 31, w = tid >> 5;
    int i = blockIdx.x * 1024 + tid;
    int v = (i < N) ? g_deg[i] : 0;
    int x = v;
#pragma unroll
    for (int d = 1; d < 32; d <<= 1) {
        int t = __shfl_up_sync(0xffffffffu, x, d);
        if (lane >= d) x += t;
    }
    if (lane == 31) sw[w] = x;
    __syncthreads();
    if (w == 0) {
        int y = sw[lane];
#pragma unroll
        for (int d = 1; d < 32; d <<= 1) {
            int t = __shfl_up_sync(0xffffffffu, y, d);
            if (lane >= d) y += t;
        }
        sw[lane] = y;
    }
    __syncthreads();
    x += ((w > 0) ? sw[w - 1] : 0) + g_bsum[blockIdx.x];
    if (i < N) { g_off[i + 1] = x; g_cur[i] = x - v; }
    if (i == 0) g_off[0] = 0;
}

__global__ void k_fill(int E) {
    int e = blockIdx.x * blockDim.x + threadIdx.x;
    if (e >= E) return;
    int p = atomicAdd(&g_cur[g_dst[e]], 1);
    g_csr[p] = g_src[e];
}

// ---------------- weight prep: all 6 matrices, one launch ---------------------
__global__ void k_wprep(const float* __restrict__ W0, const float* __restrict__ W1m,
                        const float* __restrict__ W2m, const float* __restrict__ W3,
                        const float* __restrict__ W4, const float* __restrict__ W5) {
    int i = blockIdx.x * blockDim.x + threadIdx.x;
    if (i >= 6 * 8192) return;
    int w = i >> 13;
    const float* W = (w == 0) ? W0 : (w == 1) ? W1m : (w == 2) ? W2m
                   : (w == 3) ? W3 : (w == 4) ? W4 : W5;
    int layer = w >> 1, mat = w & 1;
    int r    = i & 8191;
    int c    = r & 3;
    int vec  = r >> 2;
    int lane = vec & 31;
    int i8   = (vec >> 5) & 7;
    int ks   = vec >> 8;
    int nt = 2 * i8 + (c >> 1);
    int j  = c & 1;
    int n  = nt * 8 + (lane >> 2);
    int kb = ks * 16 + (lane & 3) * 2 + j * 8;
    float w0 = W[n * 128 + kb];
    float w1 = W[n * 128 + kb + 1];
    uint32_t hi = bfhi(w0, w1);
    uint32_t lo = bflo(w0, w1, hi);
    g_wlin[layer][mat * 2 + 0][r] = hi;
    g_wlin[layer][mat * 2 + 1][r] = lo;
}

// ---------------- gather -----------------------------------------------------

__global__ void k_gather(const float* __restrict__ xin, int sel, int N) {
    int warp = (blockIdx.x * blockDim.x + threadIdx.x) >> 5;
    int lane = threadIdx.x & 31;
    if (warp >= N) return;
    const float* H = (sel == 0) ? xin : (sel == 1 ? g_h0 : g_h1);
    const float4* H4 = reinterpret_cast<const float4*>(H);
    int s = g_off[warp], e = g_off[warp + 1];
    float4 acc = make_float4(0.f, 0.f, 0.f, 0.f);
    int i = s;
    for (; i + 2 <= e; i += 2) {
        int s0 = g_csr[i], s1 = g_csr[i + 1];
        float4 v0 = H4[s0 * 32 + lane];
        float4 v1 = H4[s1 * 32 + lane];
        acc.x += v0.x + v1.x; acc.y += v0.y + v1.y;
        acc.z += v0.z + v1.z; acc.w += v0.w + v1.w;
    }
    if (i < e) {
        float4 v = H4[g_csr[i] * 32 + lane];
        acc.x += v.x; acc.y += v.y; acc.z += v.z; acc.w += v.w;
    }
    reinterpret_cast<float4*>(g_agg)[warp * 32 + lane] = acc;
}

// ---------------- fused HMMA dual-GEMM layer ---------------------------------
// out = agg @ Wrel^T + h @ Wroot^T + bias [, relu]
// bf16-pair split (AhWh + AhWl + AlWh), f32 accumulate, mma.sync m16n8k16.
// CTA: 256 threads, 8 warps x 32 rows = 256-row tile, 128 cols.
// All 4 W segments staged once in dynamic smem (128 KB), conflict-free LDS.128.

__device__ __forceinline__ void mma16816(float* d, const uint32_t* a,
                                         uint32_t b0, uint32_t b1) {
    asm volatile(
        "mma.sync.aligned.m16n8k16.row.col.f32.bf16.bf16.f32 "
        "{%0,%1,%2,%3}, {%4,%5,%6,%7}, {%8,%9}, {%0,%1,%2,%3};"
        : "+f"(d[0]), "+f"(d[1]), "+f"(d[2]), "+f"(d[3])
        : "r"(a[0]), "r"(a[1]), "r"(a[2]), "r"(a[3]), "r"(b0), "r"(b1));
}

#define HM_SMEM (4 * 8192 * 4)   // 131072 B

__global__ void __launch_bounds__(256, 1) k_hmma(
    const float* __restrict__ xin, int selIn, int selOut,
    int layer, const float* __restrict__ bias, int N, int do_relu)
{
    extern __shared__ uint4 sw4[];   // [4 segs][2048 uint4]
    const int tid  = threadIdx.x;
    const int wid  = tid >> 5;
    const int lane = tid & 31;

    // stage all 4 W segments (128 KB) into smem
    {
        const uint4* src = reinterpret_cast<const uint4*>(g_wlin[layer]);
#pragma unroll
        for (int t = 0; t < 32; ++t) sw4[tid + t * 256] = src[tid + t * 256];
    }
    __syncthreads();

    const float* Hin = (selIn == 0) ? xin : (selIn == 1 ? g_h0 : g_h1);
    float* Hout = (selOut == 1) ? g_h0 : g_h1;

    const int row0  = blockIdx.x * 256 + wid * 32;
    const int rbase = row0 + (lane >> 2);
    const int kc    = (lane & 3) * 2;

    float acc[32][4];
#pragma unroll
    for (int t = 0; t < 32; ++t)
#pragma unroll
        for (int j = 0; j < 4; ++j) acc[t][j] = 0.f;

    uint32_t Ah[8], Al[8];

#pragma unroll 1
    for (int s = 0; s < 2; ++s) {
        const float* Asrc = s ? Hin : g_agg;
        const uint4* segHi = sw4 + (s * 2 + 0) * 2048;
        const uint4* segLo = sw4 + (s * 2 + 1) * 2048;

#pragma unroll 1
        for (int ks = 0; ks < 8; ++ks) {
            const int k0 = ks * 16 + kc;
            // build A hi/lo frags for both 16-row m-tiles
#pragma unroll
            for (int mt = 0; mt < 2; ++mt) {
                int ra = rbase + mt * 16, rb = ra + 8;
                bool va = ra < N, vb = rb < N;
                const float* pa = Asrc + (size_t)ra * 128;
                const float* pb = Asrc + (size_t)rb * 128;
                float2 z = make_float2(0.f, 0.f);
                float2 x0 = va ? *(const float2*)(pa + k0)     : z;
                float2 x1 = vb ? *(const float2*)(pb + k0)     : z;
                float2 x2 = va ? *(const float2*)(pa + k0 + 8) : z;
                float2 x3 = vb ? *(const float2*)(pb + k0 + 8) : z;
                uint32_t h0 = bfhi(x0.x, x0.y), h1 = bfhi(x1.x, x1.y);
                uint32_t h2 = bfhi(x2.x, x2.y), h3 = bfhi(x3.x, x3.y);
                Ah[mt * 4 + 0] = h0; Al[mt * 4 + 0] = bflo(x0.x, x0.y, h0);
                Ah[mt * 4 + 1] = h1; Al[mt * 4 + 1] = bflo(x1.x, x1.y, h1);
                Ah[mt * 4 + 2] = h2; Al[mt * 4 + 2] = bflo(x2.x, x2.y, h2);
                Ah[mt * 4 + 3] = h3; Al[mt * 4 + 3] = bflo(x3.x, x3.y, h3);
            }
            const uint4* rowHi = segHi + ks * 8 * 32 + lane;
            const uint4* rowLo = segLo + ks * 8 * 32 + lane;
            // pass 1: Ah x W_hi
#pragma unroll
            for (int i = 0; i < 8; ++i) {
                uint4 q = rowHi[i * 32];
                mma16816(acc[2 * i],          Ah,     q.x, q.y);
                mma16816(acc[2 * i + 1],      Ah,     q.z, q.w);
                mma16816(acc[16 + 2 * i],     Ah + 4, q.x, q.y);
                mma16816(acc[16 + 2 * i + 1], Ah + 4, q.z, q.w);
            }
            // pass 2: Ah x W_lo
#pragma unroll
            for (int i = 0; i < 8; ++i) {
                uint4 q = rowLo[i * 32];
                mma16816(acc[2 * i],          Ah,     q.x, q.y);
                mma16816(acc[2 * i + 1],      Ah,     q.z, q.w);
                mma16816(acc[16 + 2 * i],     Ah + 4, q.x, q.y);
                mma16816(acc[16 + 2 * i + 1], Ah + 4, q.z, q.w);
            }
            // pass 3: Al x W_hi
#pragma unroll
            for (int i = 0; i < 8; ++i) {
                uint4 q = rowHi[i * 32];
                mma16816(acc[2 * i],          Al,     q.x, q.y);
                mma16816(acc[2 * i + 1],      Al,     q.z, q.w);
                mma16816(acc[16 + 2 * i],     Al + 4, q.x, q.y);
                mma16816(acc[16 + 2 * i + 1], Al + 4, q.z, q.w);
            }
        }
    }

    // ---- epilogue: bias, relu, store ----
#pragma unroll
    for (int mt = 0; mt < 2; ++mt) {
        int ra = rbase + mt * 16, rb = ra + 8;
        bool va = ra < N, vb = rb < N;
#pragma unroll
        for (int nt = 0; nt < 16; ++nt) {
            int c = nt * 8 + kc;
            float2 bv = *(const float2*)(bias + c);
            float* d = acc[mt * 16 + nt];
            float o0 = d[0] + bv.x, o1 = d[1] + bv.y;
            float o2 = d[2] + bv.x, o3 = d[3] + bv.y;
            if (do_relu) {
                o0 = fmaxf(o0, 0.f); o1 = fmaxf(o1, 0.f);
                o2 = fmaxf(o2, 0.f); o3 = fmaxf(o3, 0.f);
            }
            if (va) *(float2*)(Hout + (size_t)ra * 128 + c) = make_float2(o0, o1);
            if (vb) *(float2*)(Hout + (size_t)rb * 128 + c) = make_float2(o2, o3);
        }
    }
}

// ---------------- pooling + MLP ---------------------------------------------

__global__ void k_pool() {
    int g     = blockIdx.x;
    int chunk = blockIdx.y;
    int lane  = threadIdx.x & 31;
    int grp   = threadIdx.x >> 5;
    int col   = chunk * 32 + lane;
    int s = g_gstart[g], e = g_gstart[g + 1];
    float m = -3.402823466e38f;
    for (int r = s + grp; r < e; r += 8)
        m = fmaxf(m, g_h0[(long)r * 128 + col]);
    __shared__ float smx[8][32];
    smx[grp][lane] = m;
    __syncthreads();
    if (grp == 0) {
#pragma unroll
        for (int i = 1; i < 8; ++i) m = fmaxf(m, smx[i][lane]);
        g_pool[g * 128 + col] = m;
    }
}

__global__ void k_mlp(const float* __restrict__ W1, const float* __restrict__ b1,
                      const float* __restrict__ W2, const float* __restrict__ b2,
                      float* __restrict__ out, int G) {
    int g = threadIdx.x;
    if (g >= G) return;
    float o = b2[0];
#pragma unroll
    for (int j = 0; j < 5; ++j) {
        float s = b1[j];
        for (int k = 0; k < DD; k += 4) {
            float4 p  = reinterpret_cast<const float4*>(g_pool + g * DD)[k >> 2];
            float4 ww = reinterpret_cast<const float4*>(W1 + j * DD)[k >> 2];
            s += p.x * ww.x + p.y * ww.y + p.z * ww.z + p.w * ww.w;
        }
        o += fmaxf(s, 0.f) * W2[j];
    }
    out[g] = o;
}

// ---------------- launch -----------------------------------------------------

extern "C" void kernel_launch(void* const* d_in, const int* in_sizes, int n_in,
                              void* d_out, int out_size) {
    const float* x    = (const float*)d_in[0];
    const int*   eraw = (const int*)d_in[1];
    const int*   braw = (const int*)d_in[2];
    const float* Wr1  = (const float*)d_in[3];
    const float* br1  = (const float*)d_in[4];
    const float* Wo1  = (const float*)d_in[5];
    const float* Wr2  = (const float*)d_in[6];
    const float* br2  = (const float*)d_in[7];
    const float* Wo2  = (const float*)d_in[8];
    const float* Wr3  = (const float*)d_in[9];
    const float* br3  = (const float*)d_in[10];
    const float* Wo3  = (const float*)d_in[11];
    const float* W1   = (const float*)d_in[12];
    const float* b1   = (const float*)d_in[13];
    const float* W2   = (const float*)d_in[14];
    const float* b2   = (const float*)d_in[15];
    float* out = (float*)d_out;

    const int N = in_sizes[0] / DD;
    const int E = in_sizes[1] / 2;
    const int G = out_size;

    const int nb  = (N + 255) / 256;
    const int eb  = (E + 255) / 256;
    const int nsb = (N + 1023) / 1024;
    const int gw  = (N + 7) / 8;
    const int nt256 = (N + 255) / 256;

    static cudaStream_t s2 = nullptr;
    static cudaEvent_t evFork, evW;
    if (!s2) {
        cudaStreamCreateWithFlags(&s2, cudaStreamNonBlocking);
        cudaEventCreateWithFlags(&evFork, cudaEventDisableTiming);
        cudaEventCreateWithFlags(&evW,    cudaEventDisableTiming);
        cudaFuncSetAttribute(k_hmma, cudaFuncAttributeMaxDynamicSharedMemorySize,
                             HM_SMEM);
    }

    // ---- weight prep on s2, overlapped with CSR preprocessing ----
    cudaEventRecord(evFork, 0);
    cudaStreamWaitEvent(s2, evFork, 0);
    k_wprep<<<192, 256, 0, s2>>>(Wr1, Wo1, Wr2, Wo2, Wr3, Wo3);
    cudaEventRecord(evW, s2);

    // ---- CSR + batch preprocessing ----
    k_init<<<nb, 256>>>(eraw, braw, E, N / 2, N);
    k_edges<<<eb, 256>>>(eraw, E);
    k_batch<<<nb, 256>>>(braw, N, G);
    k_scan1<<<nsb, 1024>>>(N);
    k_scan2<<<1, 32>>>(nsb);
    k_scan3<<<nsb, 1024>>>(N);
    k_fill<<<eb, 256>>>(E);

    // ---- layer 1 ----
    k_gather<<<gw, 256>>>(x, 0, N);
    cudaStreamWaitEvent(0, evW, 0);
    k_hmma<<<nt256, 256, HM_SMEM>>>(x, 0, 1, 0, br1, N, 1); // h0 = relu(agg@Wr1^T + x@Wo1^T + b1)
    // ---- layer 2 ----
    k_gather<<<gw, 256>>>(x, 1, N);
    k_hmma<<<nt256, 256, HM_SMEM>>>(x, 1, 2, 1, br2, N, 1); // h1 = relu(agg@Wr2^T + h0@Wo2^T + b2)
    // ---- layer 3 ----
    k_gather<<<gw, 256>>>(x, 2, N);
    k_hmma<<<nt256, 256, HM_SMEM>>>(x, 2, 1, 2, br3, N, 0); // h0 = agg@Wr3^T + h1@Wo3^T + b3

    // ---- pool + mlp ----
    dim3 pg(G, DD / 32);
    k_pool<<<pg, 256>>>();
    k_mlp<<<1, 64>>>(W1, b1, W2, b2, out, G);
}